// round 13
// baseline (speedup 1.0000x reference)
#include <cuda_runtime.h>
#include <cuda_bf16.h>
#include <cstdint>

// ---------------------------------------------------------------------------
// WMSA round 13: B-resident double-buffered fused GEMMs (no mid-tile syncs).
//   qkv_fused : gather+split x -> resident smem A; 9 N-tiles, B tile fully
//               resident + double buffered (2 syncs/tile, prefetch overlap)
//   attn      : unchanged (round 11/12, verified)
//   proj_fused: same structure, 3 N-tiles, scatter epilogue
// ---------------------------------------------------------------------------

#define NWINS 1024
#define TPW   64

__device__ __align__(16) __nv_bfloat16 g_qkv_hi[(size_t)NWINS * TPW * 576];
__device__ __align__(16) __nv_bfloat16 g_qkv_lo[(size_t)NWINS * TPW * 576];
__device__ __align__(16) __nv_bfloat16 g_at_hi[(size_t)NWINS * TPW * 192];
__device__ __align__(16) __nv_bfloat16 g_at_lo[(size_t)NWINS * TPW * 192];

__device__ __align__(16) __nv_bfloat16 WqkvT_hi[576 * 192];
__device__ __align__(16) __nv_bfloat16 WqkvT_lo[576 * 192];
__device__ __align__(16) __nv_bfloat16 WoutT_hi[192 * 192];
__device__ __align__(16) __nv_bfloat16 WoutT_lo[192 * 192];

// ------------------------------ helpers ------------------------------------
__device__ __forceinline__ uint32_t smem_u32(const void* p) {
    uint32_t a;
    asm("{ .reg .u64 t; cvta.to.shared.u64 t, %1; cvt.u32.u64 %0, t; }" : "=r"(a) : "l"(p));
    return a;
}
__device__ __forceinline__ uint32_t pack2(float a, float b) {
    uint32_t r;
    asm("cvt.rn.bf16x2.f32 %0, %1, %2;" : "=r"(r) : "f"(b), "f"(a));
    return r;
}
__device__ __forceinline__ void split2(float a, float b, uint32_t& h, uint32_t& l) {
    h = pack2(a, b);
    float ha = __uint_as_float(h << 16);
    float hb = __uint_as_float(h & 0xffff0000u);
    l = pack2(a - ha, b - hb);
}
__device__ __forceinline__ void split8(const float4 v0, const float4 v1,
                                       uint4& h, uint4& l) {
    uint32_t h0, l0, h1, l1, h2, l2, h3, l3;
    split2(v0.x, v0.y, h0, l0);
    split2(v0.z, v0.w, h1, l1);
    split2(v1.x, v1.y, h2, l2);
    split2(v1.z, v1.w, h3, l3);
    h = make_uint4(h0, h1, h2, h3);
    l = make_uint4(l0, l1, l2, l3);
}
__device__ __forceinline__ void ldsm_x4(uint32_t* r, uint32_t addr) {
    asm volatile("ldmatrix.sync.aligned.m8n8.x4.shared.b16 {%0,%1,%2,%3}, [%4];"
        : "=r"(r[0]), "=r"(r[1]), "=r"(r[2]), "=r"(r[3]) : "r"(addr));
}
__device__ __forceinline__ void mma_bf16(float* c, const uint32_t* a, const uint32_t* b) {
    asm volatile("mma.sync.aligned.m16n8k16.row.col.f32.bf16.bf16.f32 "
        "{%0,%1,%2,%3}, {%4,%5,%6,%7}, {%8,%9}, {%0,%1,%2,%3};"
        : "+f"(c[0]), "+f"(c[1]), "+f"(c[2]), "+f"(c[3])
        : "r"(a[0]), "r"(a[1]), "r"(a[2]), "r"(a[3]), "r"(b[0]), "r"(b[1]));
}

// dynamic smem layout (bytes):
//   AH [128][200]e = 51200, AL = 51200
//   B double buffer: 2 x (BH [64][200]e = 25600, BL = 25600)
#define SMO_AH 0
#define SMO_AL 51200
#define SMO_B0 102400
#define SM_SZ  204800

// ------------------------------ prep: weights ------------------------------
__global__ void prep_kernel(const float* __restrict__ Wqkv,
                            const float* __restrict__ Wout)
{
    int i = blockIdx.x * 256 + threadIdx.x;
    if (i < 576 * 192) {
        int n = i / 192, k = i % 192;
        float v = Wqkv[(size_t)k * 576 + n];
        __nv_bfloat16 h = __float2bfloat16(v);
        WqkvT_hi[i] = h;
        WqkvT_lo[i] = __float2bfloat16(v - __bfloat162float(h));
    }
    int j = i - 576 * 192;
    if (j >= 0 && j < 192 * 192) {
        int n = j / 192, k = j % 192;
        float v = Wout[(size_t)k * 192 + n];
        __nv_bfloat16 h = __float2bfloat16(v);
        WoutT_hi[j] = h;
        WoutT_lo[j] = __float2bfloat16(v - __bfloat162float(h));
    }
}

// ---------------------- fused GEMM (B-resident, dbl-buffered) --------------
// A resident [128][200] hi/lo; per N-tile B fully resident [64][200] hi/lo.
// NT tiles of 64 cols each, W tiles contiguous ([nt*64 .. ][192]).
template <int NT, typename EpiFn>
__device__ __forceinline__ void fused_gemm(
    uint8_t* smem, const __nv_bfloat16* __restrict__ Wh,
    const __nv_bfloat16* __restrict__ Wl, EpiFn epi)
{
    const int tid = threadIdx.x, lane = tid & 31, wid = tid >> 5;
    const int m0 = (wid & 3) * 32, n0 = (wid >> 2) * 32;

    const uint32_t sAH = smem_u32(smem + SMO_AH), sAL = smem_u32(smem + SMO_AL);
    const uint32_t sB  = smem_u32(smem + SMO_B0);

    // per-thread B-load map: 1536 uint4 units per plane, 6 per thread
    int brow[6], bcol[6];
    #pragma unroll
    for (int i = 0; i < 6; ++i) {
        int u = tid + i * 256;
        brow[i] = u / 24;
        bcol[i] = u % 24;
    }

    uint4 rh[6], rl[6];
    #pragma unroll
    for (int i = 0; i < 6; ++i) {
        rh[i] = *(const uint4*)(Wh + (size_t)brow[i] * 192 + bcol[i] * 8);
        rl[i] = *(const uint4*)(Wl + (size_t)brow[i] * 192 + bcol[i] * 8);
    }
    #pragma unroll
    for (int i = 0; i < 6; ++i) {
        *(uint4*)(smem + SMO_B0 + brow[i] * 400 + bcol[i] * 16)         = rh[i];
        *(uint4*)(smem + SMO_B0 + 25600 + brow[i] * 400 + bcol[i] * 16) = rl[i];
    }
    __syncthreads();   // covers A stores (done before call-site loads B) + B0

    for (int nt = 0; nt < NT; ++nt) {
        // prefetch next tile's B into registers (latency hidden by compute)
        if (nt + 1 < NT) {
            const __nv_bfloat16* nWh = Wh + (size_t)(nt + 1) * 64 * 192;
            const __nv_bfloat16* nWl = Wl + (size_t)(nt + 1) * 64 * 192;
            #pragma unroll
            for (int i = 0; i < 6; ++i) {
                rh[i] = *(const uint4*)(nWh + (size_t)brow[i] * 192 + bcol[i] * 8);
                rl[i] = *(const uint4*)(nWl + (size_t)brow[i] * 192 + bcol[i] * 8);
            }
        }

        const uint32_t sBH = sB + (uint32_t)(nt & 1) * 51200;
        const uint32_t sBL = sBH + 25600;

        float acc[2][4][4] = {};
        #pragma unroll
        for (int kk = 0; kk < 12; ++kk) {
            uint32_t aH[2][4], aL[2][4], bH[8], bL[8];
            #pragma unroll
            for (int mf = 0; mf < 2; ++mf) {
                uint32_t off = (uint32_t)((m0 + mf * 16 + (lane & 15)) * 400
                                          + (kk * 2 + (lane >> 4)) * 16);
                ldsm_x4(aH[mf], sAH + off);
                ldsm_x4(aL[mf], sAL + off);
            }
            #pragma unroll
            for (int nf = 0; nf < 2; ++nf) {
                uint32_t off = (uint32_t)((n0 + nf * 16 + ((lane >> 4) & 1) * 8 + (lane & 7)) * 400
                                          + (kk * 2 + ((lane >> 3) & 1)) * 16);
                ldsm_x4(&bH[nf * 4], sBH + off);
                ldsm_x4(&bL[nf * 4], sBL + off);
            }
            // pass-major: independent accumulator chains
            #pragma unroll
            for (int mf = 0; mf < 2; ++mf)
                #pragma unroll
                for (int j = 0; j < 4; ++j)
                    mma_bf16(acc[mf][j], aH[mf], &bH[j * 2]);
            #pragma unroll
            for (int mf = 0; mf < 2; ++mf)
                #pragma unroll
                for (int j = 0; j < 4; ++j)
                    mma_bf16(acc[mf][j], aH[mf], &bL[j * 2]);
            #pragma unroll
            for (int mf = 0; mf < 2; ++mf)
                #pragma unroll
                for (int j = 0; j < 4; ++j)
                    mma_bf16(acc[mf][j], aL[mf], &bH[j * 2]);
        }
        epi(nt, acc);

        if (nt + 1 < NT) {
            __syncthreads();   // all warps done reading buf[(nt+1)&1] (tile nt-1)
            uint32_t nb = SMO_B0 + (uint32_t)((nt + 1) & 1) * 51200;
            #pragma unroll
            for (int i = 0; i < 6; ++i) {
                *(uint4*)(smem + nb + brow[i] * 400 + bcol[i] * 16)         = rh[i];
                *(uint4*)(smem + nb + 25600 + brow[i] * 400 + bcol[i] * 16) = rl[i];
            }
            __syncthreads();
        }
    }
}

// ------------------------------ K1: QKV fused ------------------------------
__global__ __launch_bounds__(256) void qkv_fused(
    const float* __restrict__ x, const float* __restrict__ bqkv)
{
    extern __shared__ __align__(16) uint8_t smem[];
    const int tid = threadIdx.x, lane = tid & 31, wid = tid >> 5;
    const int mt = blockIdx.x;
    const int m0 = (wid & 3) * 32, n0 = (wid >> 2) * 32;

    {   // gather + convert: 2 threads per row, 96 floats each
        const int row = tid >> 1, half = tid & 1;
        const int rowg = mt * 128 + row;
        const int tok = rowg & 63, bw = rowg >> 6;
        const int b = bw >> 9, w = bw & 511;
        const int z  = (((w >> 6) << 2)       + (tok >> 4)       + 2) & 31;
        const int y  = ((((w >> 3) & 7) << 2) + ((tok >> 2) & 3) + 2) & 31;
        const int xx = (((w & 7) << 2)        + (tok & 3)        + 2) & 31;
        const float4* xr4 = (const float4*)(
            x + ((((size_t)b * 32 + z) * 32 + y) * 32 + xx) * 192 + half * 96);
        __nv_bfloat16* aH = (__nv_bfloat16*)(smem + SMO_AH) + row * 200 + half * 96;
        __nv_bfloat16* aL = (__nv_bfloat16*)(smem + SMO_AL) + row * 200 + half * 96;
        #pragma unroll
        for (int i = 0; i < 12; ++i) {
            uint4 h, l;
            split8(xr4[2 * i], xr4[2 * i + 1], h, l);
            *(uint4*)&aH[i * 8] = h;
            *(uint4*)&aL[i * 8] = l;
        }
    }

    const int rbase = mt * 128 + m0 + (lane >> 2);
    fused_gemm<9>(smem, WqkvT_hi, WqkvT_lo,
        [&](int nt, float acc[2][4][4]) {
            #pragma unroll
            for (int j = 0; j < 4; ++j) {
                int col = nt * 64 + n0 + j * 8 + (lane & 3) * 2;
                float b0 = __ldg(&bqkv[col]), b1 = __ldg(&bqkv[col + 1]);
                #pragma unroll
                for (int mf = 0; mf < 2; ++mf) {
                    uint32_t h0, l0, h1, l1;
                    split2(acc[mf][j][0] + b0, acc[mf][j][1] + b1, h0, l0);
                    split2(acc[mf][j][2] + b0, acc[mf][j][3] + b1, h1, l1);
                    size_t i0 = (size_t)(rbase + mf * 16) * 576 + col;
                    size_t i1 = (size_t)(rbase + mf * 16 + 8) * 576 + col;
                    *(uint32_t*)&g_qkv_hi[i0] = h0;
                    *(uint32_t*)&g_qkv_lo[i0] = l0;
                    *(uint32_t*)&g_qkv_hi[i1] = h1;
                    *(uint32_t*)&g_qkv_lo[i1] = l1;
                }
            }
        });
}

// ------------------------------ K2: attention (round 11) -------------------
__global__ __launch_bounds__(128) void attn_kernel(const float* __restrict__ relp)
{
    __shared__ __nv_bfloat16 qHs[64 * 40], qLs[64 * 40];
    __shared__ __nv_bfloat16 kHs[64 * 40], kLs[64 * 40];
    __shared__ __nv_bfloat16 vHs[32 * 72], vLs[32 * 72];
    __shared__ float relS[343];

    const int bw = blockIdx.x, h = blockIdx.y;
    const int w = bw & 511;
    const int wz = w >> 6, wy = (w >> 3) & 7, wx = w & 7;
    const int tid = threadIdx.x, lane = tid & 31, wrp = tid >> 5;
    const int mb = wrp * 16;
    const float scale = 0.17677669529663687f;

    for (int i = tid; i < 343; i += 128) relS[i] = relp[h * 343 + i];

    {
        const int srow = tid & 63, sel = tid >> 6;
        size_t base = ((size_t)bw * 64 + srow) * 576 + h * 32 + (size_t)sel * 192;
        __nv_bfloat16* dH = sel ? kHs : qHs;
        __nv_bfloat16* dL = sel ? kLs : qLs;
        #pragma unroll
        for (int u = 0; u < 4; ++u) {
            *(uint4*)&dH[srow * 40 + u * 8] = *(const uint4*)&g_qkv_hi[base + u * 8];
            *(uint4*)&dL[srow * 40 + u * 8] = *(const uint4*)&g_qkv_lo[base + u * 8];
        }
        if (tid < 64) {
            size_t vb = ((size_t)bw * 64 + tid) * 576 + h * 32 + 384;
            uint4 vh[4], vl[4];
            #pragma unroll
            for (int u = 0; u < 4; ++u) {
                vh[u] = *(const uint4*)&g_qkv_hi[vb + u * 8];
                vl[u] = *(const uint4*)&g_qkv_lo[vb + u * 8];
            }
            const __nv_bfloat16* ph = (const __nv_bfloat16*)vh;
            const __nv_bfloat16* pl = (const __nv_bfloat16*)vl;
            #pragma unroll
            for (int c = 0; c < 32; ++c) {
                vHs[c * 72 + tid] = ph[c];
                vLs[c * 72 + tid] = pl[c];
            }
        }
    }
    __syncthreads();

    const uint32_t sQH = smem_u32(qHs), sQL = smem_u32(qLs);
    const uint32_t sKH = smem_u32(kHs), sKL = smem_u32(kLs);
    const uint32_t sVH = smem_u32(vHs), sVL = smem_u32(vLs);

    float s[8][4];
    #pragma unroll
    for (int b2 = 0; b2 < 8; ++b2)
        #pragma unroll
        for (int c = 0; c < 4; ++c) s[b2][c] = 0.0f;

    #pragma unroll
    for (int ks = 0; ks < 2; ++ks) {
        uint32_t aH[4], aL[4], bH[4][4], bL[4][4];
        {
            uint32_t off = (uint32_t)((mb + (lane & 15)) * 80
                                      + (ks * 2 + (lane >> 4)) * 16);
            ldsm_x4(aH, sQH + off);
            ldsm_x4(aL, sQL + off);
        }
        #pragma unroll
        for (int grp = 0; grp < 4; ++grp) {
            uint32_t off = (uint32_t)((grp * 16 + ((lane >> 4) & 1) * 8 + (lane & 7)) * 80
                                      + (ks * 2 + ((lane >> 3) & 1)) * 16);
            ldsm_x4(bH[grp], sKH + off);
            ldsm_x4(bL[grp], sKL + off);
        }
        #pragma unroll
        for (int grp = 0; grp < 4; ++grp)
            #pragma unroll
            for (int j = 0; j < 2; ++j)
                mma_bf16(s[grp * 2 + j], aH, &bH[grp][j * 2]);
        #pragma unroll
        for (int grp = 0; grp < 4; ++grp)
            #pragma unroll
            for (int j = 0; j < 2; ++j)
                mma_bf16(s[grp * 2 + j], aH, &bL[grp][j * 2]);
        #pragma unroll
        for (int grp = 0; grp < 4; ++grp)
            #pragma unroll
            for (int j = 0; j < 2; ++j)
                mma_bf16(s[grp * 2 + j], aL, &bH[grp][j * 2]);
    }

    const int g = lane >> 2, tg2 = (lane & 3) * 2;
    int linP[2]; bool pz2[2], py2[2], px2[2];
    #pragma unroll
    for (int r = 0; r < 2; ++r) {
        int p = mb + g + r * 8;
        int pz = p >> 4, py = (p >> 2) & 3, px = p & 3;
        linP[r] = pz * 49 + py * 7 + px;
        pz2[r] = pz < 2; py2[r] = py < 2; px2[r] = px < 2;
    }
    int linQ[16]; bool qz2[16], qy2[16], qx2[16];
    #pragma unroll
    for (int nt = 0; nt < 8; ++nt)
        #pragma unroll
        for (int t = 0; t < 2; ++t) {
            int qq = nt * 8 + tg2 + t;
            int qz = qq >> 4, qy = (qq >> 2) & 3, qx = qq & 3;
            linQ[nt * 2 + t] = qz * 49 + qy * 7 + qx;
            qz2[nt * 2 + t] = qz < 2; qy2[nt * 2 + t] = qy < 2; qx2[nt * 2 + t] = qx < 2;
        }
    const bool mz = (wz == 7), my = (wy == 7), mx = (wx == 7);
    #pragma unroll
    for (int nt = 0; nt < 8; ++nt)
        #pragma unroll
        for (int r = 0; r < 2; ++r)
            #pragma unroll
            for (int t = 0; t < 2; ++t) {
                int qi = nt * 2 + t;
                float v = s[nt][r * 2 + t] * scale
                        + relS[linP[r] - linQ[qi] + 171];
                if ((mz && (pz2[r] != qz2[qi])) ||
                    (my && (py2[r] != qy2[qi])) ||
                    (mx && (px2[r] != qx2[qi]))) v = -1e30f;
                s[nt][r * 2 + t] = v;
            }

    float inv[2];
    #pragma unroll
    for (int r = 0; r < 2; ++r) {
        float mxv = -1e30f;
        #pragma unroll
        for (int nt = 0; nt < 8; ++nt)
            #pragma unroll
            for (int t = 0; t < 2; ++t)
                mxv = fmaxf(mxv, s[nt][r * 2 + t]);
        mxv = fmaxf(mxv, __shfl_xor_sync(0xffffffffu, mxv, 1));
        mxv = fmaxf(mxv, __shfl_xor_sync(0xffffffffu, mxv, 2));
        float sum = 0.0f;
        #pragma unroll
        for (int nt = 0; nt < 8; ++nt)
            #pragma unroll
            for (int t = 0; t < 2; ++t) {
                float e = __expf(s[nt][r * 2 + t] - mxv);
                s[nt][r * 2 + t] = e;
                sum += e;
            }
        sum += __shfl_xor_sync(0xffffffffu, sum, 1);
        sum += __shfl_xor_sync(0xffffffffu, sum, 2);
        inv[r] = 1.0f / sum;
    }

    float o[4][4];
    #pragma unroll
    for (int b2 = 0; b2 < 4; ++b2)
        #pragma unroll
        for (int c = 0; c < 4; ++c) o[b2][c] = 0.0f;

    #pragma unroll
    for (int ks = 0; ks < 4; ++ks) {
        uint32_t bH[2][4], bL[2][4];
        #pragma unroll
        for (int grp = 0; grp < 2; ++grp) {
            uint32_t off = (uint32_t)((grp * 16 + ((lane >> 4) & 1) * 8 + (lane & 7)) * 144
                                      + (ks * 2 + ((lane >> 3) & 1)) * 16);
            ldsm_x4(bH[grp], sVH + off);
            ldsm_x4(bL[grp], sVL + off);
        }
        uint32_t aPH[4], aPL[4];
        split2(s[2 * ks][0],     s[2 * ks][1],     aPH[0], aPL[0]);
        split2(s[2 * ks][2],     s[2 * ks][3],     aPH[1], aPL[1]);
        split2(s[2 * ks + 1][0], s[2 * ks + 1][1], aPH[2], aPL[2]);
        split2(s[2 * ks + 1][2], s[2 * ks + 1][3], aPH[3], aPL[3]);
        #pragma unroll
        for (int grp = 0; grp < 2; ++grp)
            #pragma unroll
            for (int j = 0; j < 2; ++j)
                mma_bf16(o[grp * 2 + j], aPH, &bH[grp][j * 2]);
        #pragma unroll
        for (int grp = 0; grp < 2; ++grp)
            #pragma unroll
            for (int j = 0; j < 2; ++j)
                mma_bf16(o[grp * 2 + j], aPH, &bL[grp][j * 2]);
        #pragma unroll
        for (int grp = 0; grp < 2; ++grp)
            #pragma unroll
            for (int j = 0; j < 2; ++j)
                mma_bf16(o[grp * 2 + j], aPL, &bH[grp][j * 2]);
    }

    {
        int r0 = mb + g;
        #pragma unroll
        for (int nt = 0; nt < 4; ++nt) {
            int col = h * 32 + nt * 8 + tg2;
            uint32_t h0, l0, h1, l1;
            split2(o[nt][0] * inv[0], o[nt][1] * inv[0], h0, l0);
            split2(o[nt][2] * inv[1], o[nt][3] * inv[1], h1, l1);
            size_t i0 = ((size_t)bw * 64 + r0) * 192 + col;
            size_t i1 = ((size_t)bw * 64 + r0 + 8) * 192 + col;
            *(uint32_t*)&g_at_hi[i0] = h0;
            *(uint32_t*)&g_at_lo[i0] = l0;
            *(uint32_t*)&g_at_hi[i1] = h1;
            *(uint32_t*)&g_at_lo[i1] = l1;
        }
    }
}

// ------------------------------ K3: out proj fused -------------------------
__global__ __launch_bounds__(256) void proj_fused(
    const float* __restrict__ bout, float* __restrict__ out)
{
    extern __shared__ __align__(16) uint8_t smem[];
    const int tid = threadIdx.x, lane = tid & 31, wid = tid >> 5;
    const int mt = blockIdx.x;
    const int m0 = (wid & 3) * 32, n0 = (wid >> 2) * 32;

    {   // copy A planes: 2 threads per row
        const int row = tid >> 1, half = tid & 1;
        const __nv_bfloat16* sH = g_at_hi + (size_t)(mt * 128 + row) * 192 + half * 96;
        const __nv_bfloat16* sL = g_at_lo + (size_t)(mt * 128 + row) * 192 + half * 96;
        __nv_bfloat16* aH = (__nv_bfloat16*)(smem + SMO_AH) + row * 200 + half * 96;
        __nv_bfloat16* aL = (__nv_bfloat16*)(smem + SMO_AL) + row * 200 + half * 96;
        #pragma unroll
        for (int i = 0; i < 12; ++i) {
            *(uint4*)&aH[i * 8] = *(const uint4*)&sH[i * 8];
            *(uint4*)&aL[i * 8] = *(const uint4*)&sL[i * 8];
        }
    }

    size_t obase[2][2];
    #pragma unroll
    for (int mf = 0; mf < 2; ++mf)
        #pragma unroll
        for (int rr = 0; rr < 2; ++rr) {
            int rg = mt * 128 + m0 + mf * 16 + rr * 8 + (lane >> 2);
            int tok = rg & 63, bw = rg >> 6;
            int b = bw >> 9, w = bw & 511;
            int z  = (((w >> 6) << 2)       + (tok >> 4)       + 2) & 31;
            int y  = ((((w >> 3) & 7) << 2) + ((tok >> 2) & 3) + 2) & 31;
            int xx = (((w & 7) << 2)        + (tok & 3)        + 2) & 31;
            obase[mf][rr] = ((((size_t)b * 32 + z) * 32 + y) * 32 + xx) * 192;
        }

    fused_gemm<3>(smem, WoutT_hi, WoutT_lo,
        [&](int nt, float acc[2][4][4]) {
            #pragma unroll
            for (int j = 0; j < 4; ++j) {
                int col = nt * 64 + n0 + j * 8 + (lane & 3) * 2;
                float b0 = __ldg(&bout[col]), b1 = __ldg(&bout[col + 1]);
                #pragma unroll
                for (int mf = 0; mf < 2; ++mf) {
                    *(float2*)&out[obase[mf][0] + col] =
                        make_float2(acc[mf][j][0] + b0, acc[mf][j][1] + b1);
                    *(float2*)&out[obase[mf][1] + col] =
                        make_float2(acc[mf][j][2] + b0, acc[mf][j][3] + b1);
                }
            }
        });
}

// ------------------------------- launch ------------------------------------
extern "C" void kernel_launch(void* const* d_in, const int* in_sizes, int n_in,
                              void* d_out, int out_size)
{
    const float* x    = (const float*)d_in[0];
    const float* Wqkv = (const float*)d_in[1];
    const float* bqkv = (const float*)d_in[2];
    const float* relp = (const float*)d_in[3];
    const float* Wout = (const float*)d_in[4];
    const float* bout = (const float*)d_in[5];
    float* out = (float*)d_out;

    cudaFuncSetAttribute(qkv_fused,  cudaFuncAttributeMaxDynamicSharedMemorySize, SM_SZ);
    cudaFuncSetAttribute(proj_fused, cudaFuncAttributeMaxDynamicSharedMemorySize, SM_SZ);

    prep_kernel<<<576, 256>>>(Wqkv, Wout);
    qkv_fused<<<512, 256, SM_SZ>>>(x, bqkv);
    attn_kernel<<<dim3(1024, 6), 128>>>(relp);
    proj_fused<<<512, 256, SM_SZ>>>(bout, out);
}